// round 12
// baseline (speedup 1.0000x reference)
#include <cuda_runtime.h>
#include <cstdint>

// ---------------- problem constants ----------------
#define NB 8
#define MO 12
#define DD 512
#define NO 37
#define NA 6
#define NT 3
#define EMB 128
#define NAA 100
#define NC 300
#define KK 72            // MO*NA
#define NP 5112          // KK*(KK-1)
#define FD 1536

// output layout (flattened tuple, all f32)
#define OFF_FINAL 0
#define OFF_PL    2400                       // pair_logits [8,5112,3]
#define OFF_TT    (2400 + 122688)            // tr_targets  [8,5112,3]
#define OFF_ACT   (2400 + 122688 + 122688)   // act_out [8,12,6]
#define OFF_OBJ   (OFF_ACT + 576)            // obj_out [8,12,37]

// ---------------- scratch (__device__ globals; no allocs) ----------------
__device__ float    g_nonexist[NB * NC];
__device__ unsigned g_seg[NB * NC];
__device__ float    g_inpdot[NB * MO * 6];   // [b][o][t*2+half]
__device__ float    g_oembdot[NO * 6];       // [o][t*2+half]
__device__ float    g_aembdot[NA * 6];       // [a][t*2+half]
__device__ float    g_invconst[NT];          // b_tr[t] - sum(W_tr[t,:])
__device__ unsigned g_done;                  // stage1 completion counter (zero-init)
__device__ unsigned g_pair_done;             // pair-block completion counter (zero-init)

// monotone float<->uint encode for atomicMax on floats
__device__ __forceinline__ unsigned encf(float f) {
    unsigned u = __float_as_uint(f);
    return (u & 0x80000000u) ? ~u : (u | 0x80000000u);
}
__device__ __forceinline__ float decf(unsigned u) {
    return (u & 0x80000000u) ? __uint_as_float(u & 0x7fffffffu)
                             : __uint_as_float(~u);
}

__device__ __forceinline__ float warpdot(const float* __restrict__ a,
                                         const float* __restrict__ w, int n, int lane) {
    float s = 0.f;
    for (int d = lane; d < n; d += 32) s += a[d] * w[d];
#pragma unroll
    for (int o = 16; o; o >>= 1) s += __shfl_down_sync(0xffffffffu, s, o);
    return s;  // valid on lane 0
}

// ---------------- stage1 task ranges ----------------
// Region A (warp tasks, 8 warps/block):
#define A_OBJ  3552               // 96*37
#define A_ACT  (A_OBJ + 576)      // 96*6
#define A_IND  (A_ACT + 576)      // 96*6   inp partial dots vs W_tr
#define A_OE   (A_IND + 222)      // 37*6
#define A_AE   (A_OE + 36)        // 6*6
#define A_INV  (A_AE + 3)
#define A_WARPS A_INV             // 4965
#define A_BLOCKS ((A_WARPS + 7) / 8)   // 621
// Region B: non-exist head; one block per (b, 8-class chunk)
#define NE_CHUNKS 38              // 38*8 = 304 >= 300 classes
#define B_BLOCKS (NB * NE_CHUNKS) // 304
#define NSTAGE1 (A_BLOCKS + B_BLOCKS)  // 925
#define GRID_ALL (NB + NSTAGE1)        // 933

__global__ __launch_bounds__(256)
void k_all(const float* __restrict__ inp,
           const float* __restrict__ objmask,
           const float* __restrict__ Wobj, const float* __restrict__ bobj,
           const float* __restrict__ Wact, const float* __restrict__ bact,
           const float* __restrict__ Wtr,  const float* __restrict__ btr,
           const float* __restrict__ Wne,  const float* __restrict__ bne,
           const float* __restrict__ oemb, const float* __restrict__ aemb,
           const int* __restrict__ AA,
           const float* __restrict__ TR,
           const int* __restrict__ lookup,
           float* __restrict__ out) {
    int tid = threadIdx.x;
    int lane = tid & 31;

    if (blockIdx.x >= NB) {
        // ================= STAGE 1 =================
        int sb = blockIdx.x - NB;
        if (sb < A_BLOCKS) {
            // ---- Region A: warp-per-dot tasks ----
            int warp = sb * 8 + (tid >> 5);
            if (warp < A_WARPS) {
                if (warp < A_OBJ) {
                    int c = warp % NO, bo = warp / NO;
                    float r = warpdot(inp + bo * DD, Wobj + c * DD, DD, lane);
                    if (lane == 0) out[OFF_OBJ + bo * NO + c] = r + bobj[c];
                } else if (warp < A_ACT) {
                    int t = warp - A_OBJ;
                    int c = t % NA, bo = t / NA;
                    float r = warpdot(inp + bo * DD, Wact + c * DD, DD, lane);
                    if (lane == 0) out[OFF_ACT + bo * NA + c] = r + bact[c];
                } else if (warp < A_IND) {
                    int t = warp - A_ACT;
                    int idx = t % 6, bo = t / 6;
                    int tt = idx >> 1, half = idx & 1;
                    float r = warpdot(inp + bo * DD, Wtr + tt * FD + half * 768, DD, lane);
                    if (lane == 0) g_inpdot[bo * 6 + idx] = r;
                } else if (warp < A_OE) {
                    int t = warp - A_IND;
                    int idx = t % 6, o = t / 6;
                    int tt = idx >> 1, half = idx & 1;
                    float r = warpdot(oemb + o * EMB, Wtr + tt * FD + half * 768 + DD, EMB, lane);
                    if (lane == 0) g_oembdot[o * 6 + idx] = r;
                } else if (warp < A_AE) {
                    int t = warp - A_OE;
                    int idx = t % 6, a = t / 6;
                    int tt = idx >> 1, half = idx & 1;
                    float r = warpdot(aemb + a * EMB, Wtr + tt * FD + half * 768 + DD + EMB, EMB, lane);
                    if (lane == 0) g_aembdot[a * 6 + idx] = r;
                } else {
                    int tt = warp - A_AE;
                    float s = 0.f;
                    for (int d = lane; d < FD; d += 32) s -= Wtr[tt * FD + d];
#pragma unroll
                    for (int o = 16; o; o >>= 1) s += __shfl_down_sync(0xffffffffu, s, o);
                    if (lane == 0) g_invconst[tt] = s + btr[tt];
                }
            }
        } else {
            // ---- Region B: non-exist head (pooled in smem), seg clear ----
            int rb = sb - A_BLOCKS;
            int b = rb / NE_CHUNKS;
            int chunk = rb % NE_CHUNKS;

            __shared__ float s_pool[DD];

            float msum = 0.f;
#pragma unroll
            for (int o = 0; o < MO; o++) msum += objmask[b * MO + o];
            float inv = 1.0f / msum;
#pragma unroll
            for (int r = 0; r < DD / 256; r++) {
                int d = tid + r * 256;
                float acc = 0.f;
#pragma unroll
                for (int o = 0; o < MO; o++)
                    acc += inp[(b * MO + o) * DD + d] * objmask[b * MO + o];
                s_pool[d] = acc * inv;
            }

            if (chunk == 0) {
                for (int t = tid; t < NC; t += 256) g_seg[b * NC + t] = 0u;
            }
            __syncthreads();

            int c = chunk * 8 + (tid >> 5);
            if (c < NC) {
                float r = warpdot(s_pool, Wne + c * DD, DD, lane);
                if (lane == 0) g_nonexist[b * NC + c] = r + bne[c];
            }
        }
        // release: all this block's writes, then count in
        __threadfence();
        __syncthreads();
        if (tid == 0) atomicAdd(&g_done, 1u);
        return;
    }

    // ================= PAIR PHASE (one block per batch) =================
    int b = blockIdx.x;

    // acquire: wait for all stage1 blocks
    if (tid == 0) {
        while (atomicAdd(&g_done, 0u) < NSTAGE1) {}
    }
    __syncthreads();
    __threadfence();

    __shared__ float s_dA[KK][NT], s_dB[KK][NT];
    __shared__ int s_aa[KK];
    __shared__ unsigned s_bits[3];
    __shared__ int s_am[MO];
    __shared__ float s_btr[NT], s_inv[NT];

    if (tid < MO) {
        const float* row = out + OFF_OBJ + (b * MO + tid) * NO;
        float best = __ldcg(row); int bi = 0;
#pragma unroll
        for (int c = 1; c < NO; c++) { float v = __ldcg(row + c); if (v > best) { best = v; bi = c; } }
        s_am[tid] = bi;
    }
    if (tid < NT) { s_btr[tid] = btr[tid]; s_inv[tid] = __ldcg(&g_invconst[tid]); }
    __syncthreads();

    bool sel = false;
    if (tid < KK) {
        int o = tid / NA, a = tid % NA;
        float act = __ldcg(out + OFF_ACT + b * KK + tid);
        float m = objmask[b * MO + o];
        float pa = (act > 0.f) ? m : 0.f;
        int aa = AA[b * KK + tid];
        sel = (pa == 1.0f) && (aa != -1);
        s_aa[tid] = aa;
        int po = s_am[o];
#pragma unroll
        for (int t = 0; t < NT; t++) {
            s_dA[tid][t] = __ldcg(&g_inpdot[(b * MO + o) * 6 + t * 2 + 0])
                         + __ldcg(&g_oembdot[po * 6 + t * 2 + 0])
                         + __ldcg(&g_aembdot[a * 6 + t * 2 + 0]);
            s_dB[tid][t] = __ldcg(&g_inpdot[(b * MO + o) * 6 + t * 2 + 1])
                         + __ldcg(&g_oembdot[po * 6 + t * 2 + 1])
                         + __ldcg(&g_aembdot[a * 6 + t * 2 + 1]);
        }
    }
    if (tid < 96) {
        unsigned bal = __ballot_sync(0xffffffffu, sel);
        if ((tid & 31) == 0) s_bits[tid >> 5] = bal;
    }
    __syncthreads();

    unsigned w0 = s_bits[0], w1 = s_bits[1], w2 = s_bits[2];
    int S = __popc(w0) + __popc(w1) + __popc(w2);
    int Nv = S * (S - 1);

    auto lowmask = [](int r) -> unsigned {
        return (r >= 32) ? 0xffffffffu : ((r <= 0) ? 0u : ((1u << r) - 1u));
    };

    for (int p = tid; p < NP; p += 256) {
        int i = p / (KK - 1);
        int jr = p - i * (KK - 1);
        int j = jr + (jr >= i ? 1 : 0);

        unsigned wi = (i < 32) ? w0 : ((i < 64) ? w1 : w2);
        unsigned wj = (j < 32) ? w0 : ((j < 64) ? w1 : w2);
        int vi = (wi >> (i & 31)) & 1;
        int vj = (wj >> (j & 31)) & 1;
        int pi = __popc(w0 & lowmask(i)) + __popc(w1 & lowmask(i - 32)) + __popc(w2 & lowmask(i - 64));
        int pj = __popc(w0 & lowmask(j)) + __popc(w1 & lowmask(j - 32)) + __popc(w2 & lowmask(j - 64));

        int vb = pi * (S - 1) + (vi ? (pj - (j > i ? 1 : 0)) : 0);
        bool valid = vi && vj;
        int pos = valid ? vb : (Nv + p - vb);

        float* pl = out + OFF_PL + (size_t)(b * NP + pos) * NT;
        float* tt = out + OFF_TT + (size_t)(b * NP + pos) * NT;

        if (valid) {
            int aai = s_aa[i], aaj = s_aa[j];
            const float* tr = TR + ((size_t)(b * KK + i) * KK + j) * NT;
            const int* lk = lookup + (aai * NAA + aaj) * NT;
#pragma unroll
            for (int t = 0; t < NT; t++) {
                float lg = s_dA[i][t] + s_dB[j][t] + s_btr[t];
                pl[t] = lg;
                tt[t] = tr[t];
                atomicMax(&g_seg[b * NC + lk[t]], encf(lg));
            }
        } else {
#pragma unroll
            for (int t = 0; t < NT; t++) { pl[t] = s_inv[t]; tt[t] = -1.0f; }
        }
    }

    // drain this block's seg atomics, then final select (all of batch b's
    // atomics come from this block only)
    __threadfence();
    __syncthreads();
    for (int t = tid; t < NC; t += 256) {
        unsigned u = atomicMax(&g_seg[b * NC + t], 0u);  // L2 read of final value
        out[OFF_FINAL + b * NC + t] = u ? decf(u) : __ldcg(&g_nonexist[b * NC + t]);
    }

    // reset counters for the next graph replay (last pair block only)
    __threadfence();
    __syncthreads();
    if (tid == 0) {
        if (atomicAdd(&g_pair_done, 1u) == NB - 1) {
            g_done = 0u;
            g_pair_done = 0u;
            __threadfence();
        }
    }
}

extern "C" void kernel_launch(void* const* d_in, const int* in_sizes, int n_in,
                              void* d_out, int out_size) {
    const float* inp     = (const float*)d_in[0];
    const float* objmask = (const float*)d_in[1];
    const float* TR      = (const float*)d_in[2];
    const float* Wobj    = (const float*)d_in[3];
    const float* bobj    = (const float*)d_in[4];
    const float* Wact    = (const float*)d_in[5];
    const float* bact    = (const float*)d_in[6];
    const float* Wtr     = (const float*)d_in[7];
    const float* btr     = (const float*)d_in[8];
    const float* Wne     = (const float*)d_in[9];
    const float* bne     = (const float*)d_in[10];
    const float* oemb    = (const float*)d_in[11];
    const float* aemb    = (const float*)d_in[12];
    const int*   AA      = (const int*)d_in[13];
    // d_in[14] = obj_act_lookup (eval-only branch, unused)
    const int*   lookup  = (const int*)d_in[15];
    float* out = (float*)d_out;

    k_all<<<GRID_ALL, 256>>>(inp, objmask, Wobj, bobj, Wact, bact,
                             Wtr, btr, Wne, bne, oemb, aemb,
                             AA, TR, lookup, out);
}

// round 14
// speedup vs baseline: 1.6208x; 1.6208x over previous
#include <cuda_runtime.h>
#include <cstdint>

// ---------------- problem constants ----------------
#define NB 8
#define MO 12
#define DD 512
#define NO 37
#define NA 6
#define NT 3
#define EMB 128
#define NAA 100
#define NC 300
#define KK 72            // MO*NA
#define NP 5112          // KK*(KK-1)
#define FD 1536

// output layout (flattened tuple, all f32)
#define OFF_FINAL 0
#define OFF_PL    2400                       // pair_logits [8,5112,3]
#define OFF_TT    (2400 + 122688)            // tr_targets  [8,5112,3]
#define OFF_ACT   (2400 + 122688 + 122688)   // act_out [8,12,6]
#define OFF_OBJ   (OFF_ACT + 576)            // obj_out [8,12,37]

// ---------------- scratch (__device__ globals; no allocs) ----------------
__device__ float    g_nonexist[NB * NC];
__device__ unsigned g_seg[NB * NC];          // zero-init; self-cleaned by atomicExch
__device__ float    g_inpdot[NB * MO * 6];   // [b][o][t*2+half]
__device__ float    g_oembdot[NO * 6];       // [o][t*2+half]
__device__ float    g_aembdot[NA * 6];       // [a][t*2+half]
__device__ float    g_invconst[NT];          // b_tr[t] - sum(W_tr[t,:])
__device__ unsigned g_doneA;                 // dot-block completion counter
__device__ unsigned g_doneB;                 // NE-block completion counter
__device__ unsigned g_pair_ctr[NB];          // per-batch pair-block completion
__device__ unsigned g_fin;                   // epilogue-block completion

// monotone float<->uint encode for atomicMax on floats
__device__ __forceinline__ unsigned encf(float f) {
    unsigned u = __float_as_uint(f);
    return (u & 0x80000000u) ? ~u : (u | 0x80000000u);
}
__device__ __forceinline__ float decf(unsigned u) {
    return (u & 0x80000000u) ? __uint_as_float(u & 0x7fffffffu)
                             : __uint_as_float(~u);
}

__device__ __forceinline__ float warpdot4(const float4* __restrict__ a,
                                          const float4* __restrict__ w, int n4, int lane) {
    float s = 0.f;
    for (int d = lane; d < n4; d += 32) {
        float4 x = a[d], y = w[d];
        s += x.x * y.x + x.y * y.y + x.z * y.z + x.w * y.w;
    }
#pragma unroll
    for (int o = 16; o; o >>= 1) s += __shfl_down_sync(0xffffffffu, s, o);
    return s;  // valid on lane 0
}

// ---------------- grid layout ----------------
// Region A (warp-per-dot, 8 warps/block):
#define A_OBJ  3552               // 96*37
#define A_ACT  (A_OBJ + 576)      // 96*6
#define A_IND  (A_ACT + 576)      // 96*6   inp partial dots vs W_tr
#define A_OE   (A_IND + 222)      // 37*6
#define A_AE   (A_OE + 36)        // 6*6
#define A_INV  (A_AE + 3)
#define A_WARPS A_INV             // 4965
#define A_BLOCKS ((A_WARPS + 7) / 8)   // 621
// Region B: non-exist head; one block per (b, 8-class chunk)
#define NE_CHUNKS 38              // 38*8 = 304 >= 300 classes
#define B_BLOCKS (NB * NE_CHUNKS) // 304
// Region C: pair blocks, 20 chunks per batch
#define PCHUNKS 20                // 20*256 = 5120 >= 5112
#define C_BLOCKS (NB * PCHUNKS)   // 160
#define AB_BLOCKS (A_BLOCKS + B_BLOCKS)        // 925
#define GRID_ALL (AB_BLOCKS + C_BLOCKS)        // 1085

__global__ __launch_bounds__(256)
void k_all(const float* __restrict__ inp,
           const float* __restrict__ objmask,
           const float* __restrict__ Wobj, const float* __restrict__ bobj,
           const float* __restrict__ Wact, const float* __restrict__ bact,
           const float* __restrict__ Wtr,  const float* __restrict__ btr,
           const float* __restrict__ Wne,  const float* __restrict__ bne,
           const float* __restrict__ oemb, const float* __restrict__ aemb,
           const int* __restrict__ AA,
           const float* __restrict__ TR,
           const int* __restrict__ lookup,
           float* __restrict__ out) {
    int tid = threadIdx.x;
    int lane = tid & 31;

    const float4* inp4  = (const float4*)inp;
    const float4* Wtr4  = (const float4*)Wtr;

    if (blockIdx.x < A_BLOCKS) {
        // ================= Region A: warp-per-dot =================
        int warp = blockIdx.x * 8 + (tid >> 5);
        if (warp < A_WARPS) {
            if (warp < A_OBJ) {
                int c = warp % NO, bo = warp / NO;
                float r = warpdot4(inp4 + bo * (DD / 4), (const float4*)Wobj + c * (DD / 4), DD / 4, lane);
                if (lane == 0) out[OFF_OBJ + bo * NO + c] = r + bobj[c];
            } else if (warp < A_ACT) {
                int t = warp - A_OBJ;
                int c = t % NA, bo = t / NA;
                float r = warpdot4(inp4 + bo * (DD / 4), (const float4*)Wact + c * (DD / 4), DD / 4, lane);
                if (lane == 0) out[OFF_ACT + bo * NA + c] = r + bact[c];
            } else if (warp < A_IND) {
                int t = warp - A_ACT;
                int idx = t % 6, bo = t / 6;
                int tt = idx >> 1, half = idx & 1;
                float r = warpdot4(inp4 + bo * (DD / 4), Wtr4 + tt * (FD / 4) + half * 192, DD / 4, lane);
                if (lane == 0) g_inpdot[bo * 6 + idx] = r;
            } else if (warp < A_OE) {
                int t = warp - A_IND;
                int idx = t % 6, o = t / 6;
                int tt = idx >> 1, half = idx & 1;
                float r = warpdot4((const float4*)oemb + o * (EMB / 4),
                                   Wtr4 + tt * (FD / 4) + half * 192 + (DD / 4), EMB / 4, lane);
                if (lane == 0) g_oembdot[o * 6 + idx] = r;
            } else if (warp < A_AE) {
                int t = warp - A_OE;
                int idx = t % 6, a = t / 6;
                int tt = idx >> 1, half = idx & 1;
                float r = warpdot4((const float4*)aemb + a * (EMB / 4),
                                   Wtr4 + tt * (FD / 4) + half * 192 + (DD / 4) + (EMB / 4), EMB / 4, lane);
                if (lane == 0) g_aembdot[a * 6 + idx] = r;
            } else {
                int tt = warp - A_AE;
                float s = 0.f;
                for (int d = lane; d < FD / 4; d += 32) {
                    float4 y = Wtr4[tt * (FD / 4) + d];
                    s -= y.x + y.y + y.z + y.w;
                }
#pragma unroll
                for (int o = 16; o; o >>= 1) s += __shfl_down_sync(0xffffffffu, s, o);
                if (lane == 0) g_invconst[tt] = s + btr[tt];
            }
        }
        __threadfence();
        __syncthreads();
        if (tid == 0) atomicAdd(&g_doneA, 1u);
        return;
    }

    if (blockIdx.x < AB_BLOCKS) {
        // ================= Region B: non-exist head =================
        int rb = blockIdx.x - A_BLOCKS;
        int b = rb / NE_CHUNKS;
        int chunk = rb % NE_CHUNKS;

        __shared__ float4 s_pool4[DD / 4];

        float msum = 0.f;
#pragma unroll
        for (int o = 0; o < MO; o++) msum += objmask[b * MO + o];
        float inv = 1.0f / msum;
        if (tid < DD / 4) {
            float4 acc = make_float4(0.f, 0.f, 0.f, 0.f);
#pragma unroll
            for (int o = 0; o < MO; o++) {
                float m = objmask[b * MO + o];
                float4 x = inp4[(b * MO + o) * (DD / 4) + tid];
                acc.x += x.x * m; acc.y += x.y * m; acc.z += x.z * m; acc.w += x.w * m;
            }
            acc.x *= inv; acc.y *= inv; acc.z *= inv; acc.w *= inv;
            s_pool4[tid] = acc;
        }
        __syncthreads();

        int c = chunk * 8 + (tid >> 5);
        if (c < NC) {
            float r = warpdot4(s_pool4, (const float4*)Wne + c * (DD / 4), DD / 4, lane);
            if (lane == 0) g_nonexist[b * NC + c] = r + bne[c];
        }
        __threadfence();
        __syncthreads();
        if (tid == 0) atomicAdd(&g_doneB, 1u);
        return;
    }

    // ================= Region C: pair blocks =================
    int pb = blockIdx.x - AB_BLOCKS;
    int b = pb / PCHUNKS;
    int chunk = pb % PCHUNKS;

    // acquire: wait for all dot blocks
    if (tid == 0) {
        while (atomicAdd(&g_doneA, 0u) < A_BLOCKS) { __nanosleep(32); }
    }
    __syncthreads();
    __threadfence();

    __shared__ float s_dA[KK][NT], s_dB[KK][NT];
    __shared__ int s_aa[KK];
    __shared__ unsigned s_bits[3];
    __shared__ int s_am[MO];
    __shared__ float s_btr[NT], s_inv[NT];
    __shared__ unsigned s_rank;

    if (tid < MO) {
        const float* row = out + OFF_OBJ + (b * MO + tid) * NO;
        float best = __ldcg(row); int bi = 0;
#pragma unroll
        for (int c = 1; c < NO; c++) { float v = __ldcg(row + c); if (v > best) { best = v; bi = c; } }
        s_am[tid] = bi;
    }
    if (tid < NT) { s_btr[tid] = btr[tid]; s_inv[tid] = __ldcg(&g_invconst[tid]); }
    __syncthreads();

    bool sel = false;
    if (tid < KK) {
        int o = tid / NA, a = tid % NA;
        float act = __ldcg(out + OFF_ACT + b * KK + tid);
        float m = objmask[b * MO + o];
        float pa = (act > 0.f) ? m : 0.f;
        int aa = AA[b * KK + tid];
        sel = (pa == 1.0f) && (aa != -1);
        s_aa[tid] = aa;
        int po = s_am[o];
#pragma unroll
        for (int t = 0; t < NT; t++) {
            s_dA[tid][t] = __ldcg(&g_inpdot[(b * MO + o) * 6 + t * 2 + 0])
                         + __ldcg(&g_oembdot[po * 6 + t * 2 + 0])
                         + __ldcg(&g_aembdot[a * 6 + t * 2 + 0]);
            s_dB[tid][t] = __ldcg(&g_inpdot[(b * MO + o) * 6 + t * 2 + 1])
                         + __ldcg(&g_oembdot[po * 6 + t * 2 + 1])
                         + __ldcg(&g_aembdot[a * 6 + t * 2 + 1]);
        }
    }
    if (tid < 96) {
        unsigned bal = __ballot_sync(0xffffffffu, sel);
        if ((tid & 31) == 0) s_bits[tid >> 5] = bal;
    }
    __syncthreads();

    unsigned w0 = s_bits[0], w1 = s_bits[1], w2 = s_bits[2];
    int S = __popc(w0) + __popc(w1) + __popc(w2);
    int Nv = S * (S - 1);

    auto lowmask = [](int r) -> unsigned {
        return (r >= 32) ? 0xffffffffu : ((r <= 0) ? 0u : ((1u << r) - 1u));
    };

    int p = chunk * 256 + tid;
    if (p < NP) {
        int i = p / (KK - 1);
        int jr = p - i * (KK - 1);
        int j = jr + (jr >= i ? 1 : 0);

        unsigned wi = (i < 32) ? w0 : ((i < 64) ? w1 : w2);
        unsigned wj = (j < 32) ? w0 : ((j < 64) ? w1 : w2);
        int vi = (wi >> (i & 31)) & 1;
        int vj = (wj >> (j & 31)) & 1;
        int pi = __popc(w0 & lowmask(i)) + __popc(w1 & lowmask(i - 32)) + __popc(w2 & lowmask(i - 64));
        int pj = __popc(w0 & lowmask(j)) + __popc(w1 & lowmask(j - 32)) + __popc(w2 & lowmask(j - 64));

        int vb = pi * (S - 1) + (vi ? (pj - (j > i ? 1 : 0)) : 0);
        bool valid = vi && vj;
        int pos = valid ? vb : (Nv + p - vb);

        float* pl = out + OFF_PL + (size_t)(b * NP + pos) * NT;
        float* tt = out + OFF_TT + (size_t)(b * NP + pos) * NT;

        if (valid) {
            int aai = s_aa[i], aaj = s_aa[j];
            const float* tr = TR + ((size_t)(b * KK + i) * KK + j) * NT;
            const int* lk = lookup + (aai * NAA + aaj) * NT;
#pragma unroll
            for (int t = 0; t < NT; t++) {
                float lg = s_dA[i][t] + s_dB[j][t] + s_btr[t];
                pl[t] = lg;
                tt[t] = tr[t];
                atomicMax(&g_seg[b * NC + lk[t]], encf(lg));
            }
        } else {
#pragma unroll
            for (int t = 0; t < NT; t++) { pl[t] = s_inv[t]; tt[t] = -1.0f; }
        }
    }

    // release this block's seg atomics, count in for batch b
    __threadfence();
    __syncthreads();
    if (tid == 0) s_rank = atomicAdd(&g_pair_ctr[b], 1u);
    __syncthreads();

    if (s_rank == PCHUNKS - 1) {
        // last pair block of batch b: final select (also waits for NE head)
        if (tid == 0) {
            while (atomicAdd(&g_doneB, 0u) < B_BLOCKS) { __nanosleep(32); }
        }
        __syncthreads();
        __threadfence();
        for (int t = tid; t < NC; t += 256) {
            // read final seg-max and leave g_seg clean for the next replay
            unsigned u = atomicExch(&g_seg[b * NC + t], 0u);
            out[OFF_FINAL + b * NC + t] = u ? decf(u) : __ldcg(&g_nonexist[b * NC + t]);
        }
        __threadfence();
        __syncthreads();
        if (tid == 0) {
            if (atomicAdd(&g_fin, 1u) == NB - 1) {
                // last epilogue block overall: reset all counters for next replay
                g_doneA = 0u;
                g_doneB = 0u;
#pragma unroll
                for (int bb = 0; bb < NB; bb++) g_pair_ctr[bb] = 0u;
                g_fin = 0u;
                __threadfence();
            }
        }
    }
}

extern "C" void kernel_launch(void* const* d_in, const int* in_sizes, int n_in,
                              void* d_out, int out_size) {
    const float* inp     = (const float*)d_in[0];
    const float* objmask = (const float*)d_in[1];
    const float* TR      = (const float*)d_in[2];
    const float* Wobj    = (const float*)d_in[3];
    const float* bobj    = (const float*)d_in[4];
    const float* Wact    = (const float*)d_in[5];
    const float* bact    = (const float*)d_in[6];
    const float* Wtr     = (const float*)d_in[7];
    const float* btr     = (const float*)d_in[8];
    const float* Wne     = (const float*)d_in[9];
    const float* bne     = (const float*)d_in[10];
    const float* oemb    = (const float*)d_in[11];
    const float* aemb    = (const float*)d_in[12];
    const int*   AA      = (const int*)d_in[13];
    // d_in[14] = obj_act_lookup (eval-only branch, unused)
    const int*   lookup  = (const int*)d_in[15];
    float* out = (float*)d_out;

    k_all<<<GRID_ALL, 256>>>(inp, objmask, Wobj, bobj, Wact, bact,
                             Wtr, btr, Wne, bne, oemb, aemb,
                             AA, TR, lookup, out);
}

// round 15
// speedup vs baseline: 1.9470x; 1.2013x over previous
#include <cuda_runtime.h>
#include <cstdint>

// ---------------- problem constants ----------------
#define NB 8
#define MO 12
#define DD 512
#define NO 37
#define NA 6
#define NT 3
#define EMB 128
#define NAA 100
#define NC 300
#define KK 72            // MO*NA
#define NP 5112          // KK*(KK-1)
#define FD 1536

// output layout (flattened tuple, all f32)
#define OFF_FINAL 0
#define OFF_PL    2400                       // pair_logits [8,5112,3]
#define OFF_TT    (2400 + 122688)            // tr_targets  [8,5112,3]
#define OFF_ACT   (2400 + 122688 + 122688)   // act_out [8,12,6]
#define OFF_OBJ   (OFF_ACT + 576)            // obj_out [8,12,37]

// ---------------- scratch (__device__ globals; no allocs) ----------------
__device__ float    g_nonexist[NB * NC];
__device__ unsigned g_seg[NB * NC];
__device__ float    g_inpdot[NB * MO * 6];   // [b][o][t*2+half]
__device__ float    g_oembdot[NO * 6];       // [o][t*2+half]
__device__ float    g_aembdot[NA * 6];       // [a][t*2+half]
__device__ float    g_invconst[NT];          // b_tr[t] - sum(W_tr[t,:])
__device__ unsigned g_pair_ctr[NB];          // per-batch pair-block completion

// monotone float<->uint encode for atomicMax on floats
__device__ __forceinline__ unsigned encf(float f) {
    unsigned u = __float_as_uint(f);
    return (u & 0x80000000u) ? ~u : (u | 0x80000000u);
}
__device__ __forceinline__ float decf(unsigned u) {
    return (u & 0x80000000u) ? __uint_as_float(u & 0x7fffffffu)
                             : __uint_as_float(~u);
}

__device__ __forceinline__ float warpdot4(const float4* __restrict__ a,
                                          const float4* __restrict__ w, int n4, int lane) {
    float s = 0.f;
    for (int d = lane; d < n4; d += 32) {
        float4 x = a[d], y = w[d];
        s += x.x * y.x + x.y * y.y + x.z * y.z + x.w * y.w;
    }
#pragma unroll
    for (int o = 16; o; o >>= 1) s += __shfl_down_sync(0xffffffffu, s, o);
    return s;  // valid on lane 0
}

// ---------------- K1: fused pool + all dots + seg/ctr reset ----------------
// Region A (warp tasks, 8 warps/block):
#define A_OBJ  3552               // 96*37
#define A_ACT  (A_OBJ + 576)      // 96*6
#define A_IND  (A_ACT + 576)      // 96*6   inp partial dots vs W_tr
#define A_OE   (A_IND + 222)      // 37*6
#define A_AE   (A_OE + 36)        // 6*6
#define A_INV  (A_AE + 3)
#define A_WARPS A_INV             // 4965
#define A_BLOCKS ((A_WARPS + 7) / 8)   // 621
// Region B: non-exist head; one block per (b, 8-class chunk)
#define NE_CHUNKS 38              // 38*8 = 304 >= 300 classes
#define B_BLOCKS (NB * NE_CHUNKS) // 304
#define K1_BLOCKS (A_BLOCKS + B_BLOCKS)
// pair phase
#define PCHUNKS 20                // 20*256 = 5120 >= 5112

__global__ __launch_bounds__(256)
void k_stage1(const float* __restrict__ inp,
              const float* __restrict__ objmask,
              const float* __restrict__ Wobj, const float* __restrict__ bobj,
              const float* __restrict__ Wact, const float* __restrict__ bact,
              const float* __restrict__ Wtr,  const float* __restrict__ btr,
              const float* __restrict__ Wne,  const float* __restrict__ bne,
              const float* __restrict__ oemb, const float* __restrict__ aemb,
              float* __restrict__ out) {
    int tid = threadIdx.x;
    int lane = tid & 31;
    const float4* inp4 = (const float4*)inp;
    const float4* Wtr4 = (const float4*)Wtr;

    if (blockIdx.x < A_BLOCKS) {
        // ---- Region A: warp-per-dot tasks ----
        int warp = blockIdx.x * 8 + (tid >> 5);
        if (warp >= A_WARPS) return;

        if (warp < A_OBJ) {
            int c = warp % NO, bo = warp / NO;
            float r = warpdot4(inp4 + bo * (DD / 4), (const float4*)Wobj + c * (DD / 4), DD / 4, lane);
            if (lane == 0) out[OFF_OBJ + bo * NO + c] = r + bobj[c];
        } else if (warp < A_ACT) {
            int t = warp - A_OBJ;
            int c = t % NA, bo = t / NA;
            float r = warpdot4(inp4 + bo * (DD / 4), (const float4*)Wact + c * (DD / 4), DD / 4, lane);
            if (lane == 0) out[OFF_ACT + bo * NA + c] = r + bact[c];
        } else if (warp < A_IND) {
            int t = warp - A_ACT;
            int idx = t % 6, bo = t / 6;
            int tt = idx >> 1, half = idx & 1;
            float r = warpdot4(inp4 + bo * (DD / 4), Wtr4 + tt * (FD / 4) + half * 192, DD / 4, lane);
            if (lane == 0) g_inpdot[bo * 6 + idx] = r;
        } else if (warp < A_OE) {
            int t = warp - A_IND;
            int idx = t % 6, o = t / 6;
            int tt = idx >> 1, half = idx & 1;
            float r = warpdot4((const float4*)oemb + o * (EMB / 4),
                               Wtr4 + tt * (FD / 4) + half * 192 + (DD / 4), EMB / 4, lane);
            if (lane == 0) g_oembdot[o * 6 + idx] = r;
        } else if (warp < A_AE) {
            int t = warp - A_OE;
            int idx = t % 6, a = t / 6;
            int tt = idx >> 1, half = idx & 1;
            float r = warpdot4((const float4*)aemb + a * (EMB / 4),
                               Wtr4 + tt * (FD / 4) + half * 192 + (DD / 4) + (EMB / 4), EMB / 4, lane);
            if (lane == 0) g_aembdot[a * 6 + idx] = r;
        } else {
            int tt = warp - A_AE;
            float s = 0.f;
            for (int d = lane; d < FD / 4; d += 32) {
                float4 y = Wtr4[tt * (FD / 4) + d];
                s -= y.x + y.y + y.z + y.w;
            }
#pragma unroll
            for (int o = 16; o; o >>= 1) s += __shfl_down_sync(0xffffffffu, s, o);
            if (lane == 0) g_invconst[tt] = s + btr[tt];
        }
    } else {
        // ---- Region B: non-exist head (pooled in smem), seg clear, ctr reset ----
        int rb = blockIdx.x - A_BLOCKS;
        int b = rb / NE_CHUNKS;
        int chunk = rb % NE_CHUNKS;

        __shared__ float4 s_pool4[DD / 4];

        float msum = 0.f;
#pragma unroll
        for (int o = 0; o < MO; o++) msum += objmask[b * MO + o];
        float inv = 1.0f / msum;
        if (tid < DD / 4) {
            float4 acc = make_float4(0.f, 0.f, 0.f, 0.f);
#pragma unroll
            for (int o = 0; o < MO; o++) {
                float m = objmask[b * MO + o];
                float4 x = inp4[(b * MO + o) * (DD / 4) + tid];
                acc.x += x.x * m; acc.y += x.y * m; acc.z += x.z * m; acc.w += x.w * m;
            }
            acc.x *= inv; acc.y *= inv; acc.z *= inv; acc.w *= inv;
            s_pool4[tid] = acc;
        }

        if (chunk == 0) {
            for (int t = tid; t < NC; t += 256) g_seg[b * NC + t] = 0u;
            if (tid == 0) g_pair_ctr[b] = 0u;
        }
        __syncthreads();

        int c = chunk * 8 + (tid >> 5);
        if (c < NC) {
            float r = warpdot4(s_pool4, (const float4*)Wne + c * (DD / 4), DD / 4, lane);
            if (lane == 0) g_nonexist[b * NC + c] = r + bne[c];
        }
    }
}

// ---------------- K2: pairs (PDL) + fused per-batch final epilogue ----------------
__global__ __launch_bounds__(256)
void k_pairs(const float* __restrict__ objmask,
             const int* __restrict__ AA,
             const float* __restrict__ TR,
             const int* __restrict__ lookup,
             const float* __restrict__ btr,
             float* __restrict__ out) {
    int b = blockIdx.x;
    int tid = threadIdx.x;
    int lane = tid & 31;
    int wid = tid >> 5;

    __shared__ float s_dA[KK][NT], s_dB[KK][NT];
    __shared__ int s_aa[KK];
    __shared__ unsigned s_bits[3];
    __shared__ int s_am[MO];
    __shared__ float s_btr[NT], s_inv[NT];
    __shared__ unsigned s_rank;

    // -------- independent prologue (overlaps with stage1 under PDL) --------
    int aa_mine = (tid < KK) ? AA[b * KK + tid] : -1;       // input, independent
    float m_mine = (tid < KK) ? objmask[b * MO + tid / NA] : 0.f;
    if (tid < NT) s_btr[tid] = btr[tid];

    int p = blockIdx.y * 256 + tid;
    int i = p / (KK - 1);
    int jr = p - i * (KK - 1);
    int j = jr + (jr >= i ? 1 : 0);

    // -------- wait for stage1 to fully complete (PDL grid sync) --------
    cudaGridDependencySynchronize();

    // parallel argmax: warp w handles objects o = w, w+8
    for (int o = wid; o < MO; o += 8) {
        const float* row = out + OFF_OBJ + (b * MO + o) * NO;
        float v = row[lane]; int idx = lane;                 // all lanes < 37
        if (lane + 32 < NO) {
            float x = row[lane + 32];
            if (x > v) { v = x; idx = lane + 32; }           // lane+32 > lane: keep first on tie
        }
#pragma unroll
        for (int off = 16; off; off >>= 1) {
            float v2 = __shfl_down_sync(0xffffffffu, v, off);
            int i2 = __shfl_down_sync(0xffffffffu, idx, off);
            if (v2 > v || (v2 == v && i2 < idx)) { v = v2; idx = i2; }
        }
        if (lane == 0) s_am[o] = idx;
    }
    if (tid < NT) s_inv[tid] = g_invconst[tid];
    __syncthreads();

    bool sel = false;
    if (tid < KK) {
        int o = tid / NA, a = tid % NA;
        float act = out[OFF_ACT + b * KK + tid];
        float pa = (act > 0.f) ? m_mine : 0.f;
        sel = (pa == 1.0f) && (aa_mine != -1);
        s_aa[tid] = aa_mine;
        int po = s_am[o];
#pragma unroll
        for (int t = 0; t < NT; t++) {
            s_dA[tid][t] = g_inpdot[(b * MO + o) * 6 + t * 2 + 0]
                         + g_oembdot[po * 6 + t * 2 + 0]
                         + g_aembdot[a * 6 + t * 2 + 0];
            s_dB[tid][t] = g_inpdot[(b * MO + o) * 6 + t * 2 + 1]
                         + g_oembdot[po * 6 + t * 2 + 1]
                         + g_aembdot[a * 6 + t * 2 + 1];
        }
    }
    if (tid < 96) {
        unsigned bal = __ballot_sync(0xffffffffu, sel);
        if ((tid & 31) == 0) s_bits[tid >> 5] = bal;
    }
    __syncthreads();

    unsigned w0 = s_bits[0], w1 = s_bits[1], w2 = s_bits[2];
    int S = __popc(w0) + __popc(w1) + __popc(w2);
    int Nv = S * (S - 1);

    auto lowmask = [](int r) -> unsigned {
        return (r >= 32) ? 0xffffffffu : ((r <= 0) ? 0u : ((1u << r) - 1u));
    };

    if (p < NP) {
        unsigned wi = (i < 32) ? w0 : ((i < 64) ? w1 : w2);
        unsigned wj = (j < 32) ? w0 : ((j < 64) ? w1 : w2);
        int vi = (wi >> (i & 31)) & 1;
        int vj = (wj >> (j & 31)) & 1;
        int pi = __popc(w0 & lowmask(i)) + __popc(w1 & lowmask(i - 32)) + __popc(w2 & lowmask(i - 64));
        int pj = __popc(w0 & lowmask(j)) + __popc(w1 & lowmask(j - 32)) + __popc(w2 & lowmask(j - 64));

        int vb = pi * (S - 1) + (vi ? (pj - (j > i ? 1 : 0)) : 0);
        bool valid = vi && vj;
        int pos = valid ? vb : (Nv + p - vb);

        float* pl = out + OFF_PL + (size_t)(b * NP + pos) * NT;
        float* tt = out + OFF_TT + (size_t)(b * NP + pos) * NT;

        if (valid) {
            int aai = s_aa[i], aaj = s_aa[j];
            const float* tr = TR + ((size_t)(b * KK + i) * KK + j) * NT;
            const int* lk = lookup + (aai * NAA + aaj) * NT;
#pragma unroll
            for (int t = 0; t < NT; t++) {
                float lg = s_dA[i][t] + s_dB[j][t] + s_btr[t];
                pl[t] = lg;
                tt[t] = tr[t];
                atomicMax(&g_seg[b * NC + lk[t]], encf(lg));
            }
        } else {
#pragma unroll
            for (int t = 0; t < NT; t++) { pl[t] = s_inv[t]; tt[t] = -1.0f; }
        }
    }

    // ---- fused final epilogue: last block of this batch does the select ----
    __threadfence();           // make this block's g_seg atomics device-visible
    __syncthreads();
    if (tid == 0) s_rank = atomicAdd(&g_pair_ctr[b], 1u);
    __syncthreads();
    if (s_rank == gridDim.y - 1) {
        __threadfence();       // see every other block's g_seg updates
        for (int t = tid; t < NC; t += 256) {
            unsigned u = g_seg[b * NC + t];
            out[OFF_FINAL + b * NC + t] = u ? decf(u) : g_nonexist[b * NC + t];
        }
    }
}

extern "C" void kernel_launch(void* const* d_in, const int* in_sizes, int n_in,
                              void* d_out, int out_size) {
    const float* inp     = (const float*)d_in[0];
    const float* objmask = (const float*)d_in[1];
    const float* TR      = (const float*)d_in[2];
    const float* Wobj    = (const float*)d_in[3];
    const float* bobj    = (const float*)d_in[4];
    const float* Wact    = (const float*)d_in[5];
    const float* bact    = (const float*)d_in[6];
    const float* Wtr     = (const float*)d_in[7];
    const float* btr     = (const float*)d_in[8];
    const float* Wne     = (const float*)d_in[9];
    const float* bne     = (const float*)d_in[10];
    const float* oemb    = (const float*)d_in[11];
    const float* aemb    = (const float*)d_in[12];
    const int*   AA      = (const int*)d_in[13];
    // d_in[14] = obj_act_lookup (eval-only branch, unused)
    const int*   lookup  = (const int*)d_in[15];
    float* out = (float*)d_out;

    k_stage1<<<K1_BLOCKS, 256>>>(inp, objmask, Wobj, bobj, Wact, bact,
                                 Wtr, btr, Wne, bne, oemb, aemb, out);

    // PDL: launch k_pairs while k_stage1 is still running; the in-kernel
    // cudaGridDependencySynchronize() provides the ordering + visibility.
    cudaLaunchConfig_t cfg = {};
    cfg.gridDim = dim3(NB, PCHUNKS, 1);
    cfg.blockDim = dim3(256, 1, 1);
    cfg.dynamicSmemBytes = 0;
    cfg.stream = 0;
    cudaLaunchAttribute attr[1];
    attr[0].id = cudaLaunchAttributeProgrammaticStreamSerialization;
    attr[0].val.programmaticStreamSerializationAllowed = 1;
    cfg.attrs = attr;
    cfg.numAttrs = 1;
    cudaLaunchKernelEx(&cfg, k_pairs, objmask, AA, TR, lookup, btr, out);
}